// round 7
// baseline (speedup 1.0000x reference)
#include <cuda_runtime.h>
#include <math.h>

// Problem constants
#define B_   2
#define H_   1080
#define W_   1920
#define SH_  540
#define SW_  960
#define HW_  (H_*W_)
#define SHW_ (SH_*SW_)

// Scratch (device globals — no allocations allowed)
__device__ float  g_luma[B_*SHW_];
__device__ float2 g_grad_half[B_*SHW_];

// constant-shift sobel weights (shift = offset*(N-1)/N, always < 1)
#define SXE ((float)(SW_-1)/(float)SW_)        // edge sobel, offset 1.0
#define SYE ((float)(SH_-1)/(float)SH_)
#define SXG (0.5f*(float)(SW_-1)/(float)SW_)   // grad sobel, offset 0.5
#define SYG (0.5f*(float)(SH_-1)/(float)SH_)

// gaussian sigma=1 5-tap
#define GW0 0.4026199469f
#define GW1 0.2442013420f
#define GW2 0.0544886845f

__device__ __forceinline__ int iclamp(int v, int lo, int hi) {
    return min(max(v, lo), hi);
}

// ---------------------------------------------------------------------------
// k1: luma + downsample 1080x1920 -> 540x960 (align_corners)
// ---------------------------------------------------------------------------
__global__ void __launch_bounds__(256) k_luma_half(const float* __restrict__ img) {
    int j = blockIdx.x * 32 + threadIdx.x;
    int i = blockIdx.y * 8  + threadIdx.y;
    int b = blockIdx.z;
    if (j >= SW_ || i >= SH_) return;

    float ys = fminf((float)i * (1079.0f / 539.0f), 1079.0f);
    float xs = fminf((float)j * (1919.0f / 959.0f), 1919.0f);
    int y0 = (int)ys, x0 = (int)xs;
    int y1 = min(y0 + 1, H_ - 1), x1 = min(x0 + 1, W_ - 1);
    float wy = ys - (float)y0, wx = xs - (float)x0;

    const float* r0c = img + (size_t)b * 3 * HW_;
    const float* g0c = r0c + HW_;
    const float* b0c = r0c + 2 * HW_;

    int i00 = y0 * W_ + x0, i01 = y0 * W_ + x1, i10 = y1 * W_ + x0, i11 = y1 * W_ + x1;
    float v00 = 0.299f*__ldg(r0c+i00) + 0.587f*__ldg(g0c+i00) + 0.114f*__ldg(b0c+i00);
    float v01 = 0.299f*__ldg(r0c+i01) + 0.587f*__ldg(g0c+i01) + 0.114f*__ldg(b0c+i01);
    float v10 = 0.299f*__ldg(r0c+i10) + 0.587f*__ldg(g0c+i10) + 0.114f*__ldg(b0c+i10);
    float v11 = 0.299f*__ldg(r0c+i11) + 0.587f*__ldg(g0c+i11) + 0.114f*__ldg(b0c+i11);

    float v = (v00 * (1.f - wx) + v01 * wx) * (1.f - wy)
            + (v10 * (1.f - wx) + v11 * wx) * wy;
    g_luma[(size_t)b * SHW_ + i * SW_ + j] = v;
}

// ---------------------------------------------------------------------------
// k2: fused field kernel on 32x32 tiles (4 outputs/thread):
//     luma tile -> edge sobel -> gaussian H -> gaussian V -> grad sobel
// ---------------------------------------------------------------------------
__global__ void __launch_bounds__(256) k_field() {
    __shared__ float sL[40][41];
    __shared__ float sE[38][39];
    __shared__ float sH[38][35];
    __shared__ float sV[34][35];

    int j0 = blockIdx.x * 32;
    int i0 = blockIdx.y * 32;
    int b  = blockIdx.z;
    int tid = threadIdx.y * 32 + threadIdx.x;

    const float* lp = g_luma + (size_t)b * SHW_;

    for (int t = tid; t < 40 * 40; t += 256) {
        int r = t / 40, c = t % 40;
        int gi = iclamp(i0 - 4 + r, 0, SH_ - 1);
        int gj = iclamp(j0 - 4 + c, 0, SW_ - 1);
        sL[r][c] = __ldg(lp + (size_t)gi * SW_ + gj);
    }
    __syncthreads();

    for (int t = tid; t < 38 * 38; t += 256) {
        int er = t / 38, ec = t % 38;
        int ci = iclamp(i0 - 3 + er, 0, SH_ - 1);
        int cj = iclamp(j0 - 3 + ec, 0, SW_ - 1);
        int rm = max(ci - 1, 0)        - (i0 - 4);
        int rc = ci                    - (i0 - 4);
        int rp = min(ci + 1, SH_ - 1)  - (i0 - 4);
        int cm = max(cj - 1, 0)        - (j0 - 4);
        int cc = cj                    - (j0 - 4);
        int cp = min(cj + 1, SW_ - 1)  - (j0 - 4);

        float gxm = SXE * (sL[rm][cp] - sL[rm][cm]);
        float gxc = SXE * (sL[rc][cp] - sL[rc][cm]);
        float gxp = SXE * (sL[rp][cp] - sL[rp][cm]);
        float gsm = SXE * (sL[rm][cm] + sL[rm][cp]) + (4.f - 2.f * SXE) * sL[rm][cc];
        float gsp = SXE * (sL[rp][cm] + sL[rp][cp]) + (4.f - 2.f * SXE) * sL[rp][cc];

        float xg = 0.125f * (SYE * (gxm + gxp) + (4.f - 2.f * SYE) * gxc);
        float yg = 0.125f * SYE * (gsp - gsm);
        float m2 = xg * xg + yg * yg;
        sE[er][ec] = exp2f(0.35f * __log2f(m2));   // (m2)^0.35 == mag^0.7
    }
    __syncthreads();

    for (int t = tid; t < 38 * 34; t += 256) {
        int hr = t / 34, hc = t % 34;
        int cj = iclamp(j0 - 1 + hc, 0, SW_ - 1);
        int c0 = max(cj - 2, 0)       - (j0 - 3);
        int c1 = max(cj - 1, 0)       - (j0 - 3);
        int c2 = cj                   - (j0 - 3);
        int c3 = min(cj + 1, SW_ - 1) - (j0 - 3);
        int c4 = min(cj + 2, SW_ - 1) - (j0 - 3);
        sH[hr][hc] = GW2 * (sE[hr][c0] + sE[hr][c4])
                   + GW1 * (sE[hr][c1] + sE[hr][c3])
                   + GW0 * sE[hr][c2];
    }
    __syncthreads();

    for (int t = tid; t < 34 * 34; t += 256) {
        int vr = t / 34, hc = t % 34;
        int ci = iclamp(i0 - 1 + vr, 0, SH_ - 1);
        int r0 = max(ci - 2, 0)       - (i0 - 3);
        int r1 = max(ci - 1, 0)       - (i0 - 3);
        int r2 = ci                   - (i0 - 3);
        int r3 = min(ci + 1, SH_ - 1) - (i0 - 3);
        int r4 = min(ci + 2, SH_ - 1) - (i0 - 3);
        sV[vr][hc] = GW2 * (sH[r0][hc] + sH[r4][hc])
                   + GW1 * (sH[r1][hc] + sH[r3][hc])
                   + GW0 * sH[r2][hc];
    }
    __syncthreads();

    for (int t = tid; t < 32 * 32; t += 256) {
        int gr = t / 32, gc = t % 32;
        int i = i0 + gr, j = j0 + gc;
        if (i >= SH_ || j >= SW_) continue;
        int rm = max(i - 1, 0)        - (i0 - 1);
        int rc = i                    - (i0 - 1);
        int rp = min(i + 1, SH_ - 1)  - (i0 - 1);
        int cm = max(j - 1, 0)        - (j0 - 1);
        int cc = j                    - (j0 - 1);
        int cp = min(j + 1, SW_ - 1)  - (j0 - 1);

        float gxm = SXG * (sV[rm][cp] - sV[rm][cm]);
        float gxc = SXG * (sV[rc][cp] - sV[rc][cm]);
        float gxp = SXG * (sV[rp][cp] - sV[rp][cm]);
        float gsm = SXG * (sV[rm][cm] + sV[rm][cp]) + (4.f - 2.f * SXG) * sV[rm][cc];
        float gsp = SXG * (sV[rp][cm] + sV[rp][cp]) + (4.f - 2.f * SXG) * sV[rp][cc];

        float xg = 0.125f * (SYG * (gxm + gxp) + (4.f - 2.f * SYG) * gxc);
        float yg = 0.125f * SYG * (gsp - gsm);
        g_grad_half[(size_t)b * SHW_ + (size_t)i * SW_ + j] = make_float2(xg, yg);
    }
}

// ---------------------------------------------------------------------------
// k3: fused resize + warp + sample, 32x16 tile, 2 px/thread.
//     The 6-iteration loop runs entirely in REGISTERS: drift < 0.6 px means
//     all taps live in the 3x3 lattice patch centered at the thread's pixel.
//     Read that patch once from smem, select corners with nested FSELs.
// ---------------------------------------------------------------------------
#define SMW 34
#define SMH 18

__device__ __forceinline__ float2 fsel2(bool c, float2 a, float2 b) {
    return make_float2(c ? a.x : b.x, c ? a.y : b.y);
}

__global__ void __launch_bounds__(256) k_warp_fused(const float* __restrict__ img,
                                                    float* __restrict__ out) {
    __shared__ float2 sg[SMH][SMW];

    int j0 = blockIdx.x * 32;
    int i0 = blockIdx.y * 16;
    int b  = blockIdx.z;
    int tx = threadIdx.x, ty = threadIdx.y;
    int tid = ty * 32 + tx;

    const float2* gh = g_grad_half + (size_t)b * SHW_;

    // fill full-res grad lattice patch [i0-1, i0+16] x [j0-1, j0+32]
    for (int t = tid; t < SMW * SMH; t += 256) {
        int sy = t / SMW, sx = t % SMW;
        int I = iclamp(i0 - 1 + sy, 0, H_ - 1);
        int J = iclamp(j0 - 1 + sx, 0, W_ - 1);

        float ys = fminf((float)I * (539.0f / 1079.0f), (float)(SH_ - 1));
        float xs = fminf((float)J * (959.0f / 1919.0f), (float)(SW_ - 1));
        int y0 = (int)ys, x0 = (int)xs;
        int y1 = min(y0 + 1, SH_ - 1), x1 = min(x0 + 1, SW_ - 1);
        float wy = ys - (float)y0, wx = xs - (float)x0;

        float2 v00 = __ldg(&gh[(size_t)y0 * SW_ + x0]);
        float2 v01 = __ldg(&gh[(size_t)y0 * SW_ + x1]);
        float2 v10 = __ldg(&gh[(size_t)y1 * SW_ + x0]);
        float2 v11 = __ldg(&gh[(size_t)y1 * SW_ + x1]);
        float2 r;
        r.x = (v00.x * (1.f - wx) + v01.x * wx) * (1.f - wy)
            + (v10.x * (1.f - wx) + v11.x * wx) * wy;
        r.y = (v00.y * (1.f - wx) + v01.y * wx) * (1.f - wy)
            + (v10.y * (1.f - wx) + v11.y * wx) * wy;
        sg[sy][sx] = r;
    }
    __syncthreads();

    int j = j0 + tx;
    int iA = i0 + ty;
    int iB = i0 + ty + 8;

    // 3x3 register patches: patch row k = lattice row (ty + [0|8] + k),
    // patch col k = lattice col (tx + k)
    float2 pA[3][3], pB[3][3];
#pragma unroll
    for (int r = 0; r < 3; r++)
#pragma unroll
        for (int c = 0; c < 3; c++) {
            pA[r][c] = sg[ty + r][tx + c];
            pB[r][c] = sg[ty + 8 + r][tx + c];
        }

    const float stx = 0.1f * (float)(W_ - 1) / (float)W_;
    const float sty = 0.1f * (float)(H_ - 1) / (float)H_;

    float pxA = (float)j, pyA = (float)iA;
    float pxB = (float)j, pyB = (float)iB;

#pragma unroll
    for (int it = 0; it < 6; it++) {
        // ---- chain A ----
        {
            float xc = fminf(fmaxf(pxA, 0.f), (float)(W_ - 1));
            float yc = fminf(fmaxf(pyA, 0.f), (float)(H_ - 1));
            int x0 = (int)xc, y0 = (int)yc;
            float wx = xc - (float)x0, wy = yc - (float)y0;
            bool ix = (x0 - (j - 1)) > 0;   // x0 in {j-1, j}
            bool iy = (y0 - (iA - 1)) > 0;  // y0 in {iA-1, iA}
            // select rows (iy), then columns (ix)
            float2 a0 = fsel2(iy, pA[1][0], pA[0][0]);
            float2 a1 = fsel2(iy, pA[1][1], pA[0][1]);
            float2 a2 = fsel2(iy, pA[1][2], pA[0][2]);
            float2 b0 = fsel2(iy, pA[2][0], pA[1][0]);
            float2 b1 = fsel2(iy, pA[2][1], pA[1][1]);
            float2 b2 = fsel2(iy, pA[2][2], pA[1][2]);
            float2 v00 = fsel2(ix, a1, a0), v01 = fsel2(ix, a2, a1);
            float2 v10 = fsel2(ix, b1, b0), v11 = fsel2(ix, b2, b1);
            float dx = (v00.x * (1.f - wx) + v01.x * wx) * (1.f - wy)
                     + (v10.x * (1.f - wx) + v11.x * wx) * wy;
            float dy = (v00.y * (1.f - wx) + v01.y * wx) * (1.f - wy)
                     + (v10.y * (1.f - wx) + v11.y * wx) * wy;
            float inv = 1.f / (sqrtf(dx * dx + dy * dy) + 0.01f);
            pxA -= dx * inv * stx;
            pyA -= dy * inv * sty;
        }
        // ---- chain B (independent) ----
        {
            float xc = fminf(fmaxf(pxB, 0.f), (float)(W_ - 1));
            float yc = fminf(fmaxf(pyB, 0.f), (float)(H_ - 1));
            int x0 = (int)xc, y0 = (int)yc;
            float wx = xc - (float)x0, wy = yc - (float)y0;
            bool ix = (x0 - (j - 1)) > 0;
            bool iy = (y0 - (iB - 1)) > 0;   // dead rows (iB>=H) give garbage, unused
            float2 a0 = fsel2(iy, pB[1][0], pB[0][0]);
            float2 a1 = fsel2(iy, pB[1][1], pB[0][1]);
            float2 a2 = fsel2(iy, pB[1][2], pB[0][2]);
            float2 b0 = fsel2(iy, pB[2][0], pB[1][0]);
            float2 b1 = fsel2(iy, pB[2][1], pB[1][1]);
            float2 b2 = fsel2(iy, pB[2][2], pB[1][2]);
            float2 v00 = fsel2(ix, a1, a0), v01 = fsel2(ix, a2, a1);
            float2 v10 = fsel2(ix, b1, b0), v11 = fsel2(ix, b2, b1);
            float dx = (v00.x * (1.f - wx) + v01.x * wx) * (1.f - wy)
                     + (v10.x * (1.f - wx) + v11.x * wx) * wy;
            float dy = (v00.y * (1.f - wx) + v01.y * wx) * (1.f - wy)
                     + (v10.y * (1.f - wx) + v11.y * wx) * wy;
            float inv = 1.f / (sqrtf(dx * dx + dy * dy) + 0.01f);
            pxB -= dx * inv * stx;
            pyB -= dy * inv * sty;
        }
    }

    // final image sample (3 channels, global/L1) + clip, both rows
#pragma unroll
    for (int s = 0; s < 2; s++) {
        int i = (s == 0) ? iA : iB;
        if (i >= H_) break;
        float px = (s == 0) ? pxA : pxB;
        float py = (s == 0) ? pyA : pyB;

        float xc = fminf(fmaxf(px, 0.f), (float)(W_ - 1));
        float yc = fminf(fmaxf(py, 0.f), (float)(H_ - 1));
        int x0 = (int)xc, y0 = (int)yc;
        int x1 = min(x0 + 1, W_ - 1), y1 = min(y0 + 1, H_ - 1);
        float wx = xc - (float)x0, wy = yc - (float)y0;
        float w00 = (1.f - wx) * (1.f - wy), w01 = wx * (1.f - wy);
        float w10 = (1.f - wx) * wy,         w11 = wx * wy;
        size_t i00 = (size_t)y0 * W_ + x0, i01 = (size_t)y0 * W_ + x1;
        size_t i10 = (size_t)y1 * W_ + x0, i11 = (size_t)y1 * W_ + x1;

#pragma unroll
        for (int c = 0; c < 3; c++) {
            const float* plane = img + ((size_t)b * 3 + c) * HW_;
            float v = __ldg(plane + i00) * w00 + __ldg(plane + i01) * w01
                    + __ldg(plane + i10) * w10 + __ldg(plane + i11) * w11;
            v = fminf(fmaxf(v, 0.f), 1.f);
            out[((size_t)b * 3 + c) * HW_ + (size_t)i * W_ + j] = v;
        }
    }
}

// ---------------------------------------------------------------------------
extern "C" void kernel_launch(void* const* d_in, const int* in_sizes, int n_in,
                              void* d_out, int out_size) {
    const float* img = (const float*)d_in[0];
    float* out = (float*)d_out;

    dim3 blk(32, 8, 1);
    dim3 gridL((SW_ + 31) / 32, (SH_ + 7) / 8, B_);
    dim3 gridS((SW_ + 31) / 32, (SH_ + 31) / 32, B_);
    dim3 gridF(W_ / 32, (H_ + 15) / 16, B_);

    k_luma_half <<<gridL, blk>>>(img);
    k_field     <<<gridS, blk>>>();
    k_warp_fused<<<gridF, blk>>>(img, out);
}

// round 8
// speedup vs baseline: 1.1450x; 1.1450x over previous
#include <cuda_runtime.h>
#include <math.h>

// Problem constants
#define B_   2
#define H_   1080
#define W_   1920
#define SH_  540
#define SW_  960
#define HW_  (H_*W_)
#define SHW_ (SH_*SW_)

// Scratch (device globals — no allocations allowed)
__device__ float  g_luma[B_*SHW_];
__device__ float2 g_grad_half[B_*SHW_];

// constant-shift sobel weights (shift = offset*(N-1)/N, always < 1)
#define SXE ((float)(SW_-1)/(float)SW_)        // edge sobel, offset 1.0
#define SYE ((float)(SH_-1)/(float)SH_)
#define SXG (0.5f*(float)(SW_-1)/(float)SW_)   // grad sobel, offset 0.5
#define SYG (0.5f*(float)(SH_-1)/(float)SH_)

// gaussian sigma=1 5-tap
#define GW0 0.4026199469f
#define GW1 0.2442013420f
#define GW2 0.0544886845f

__device__ __forceinline__ int iclamp(int v, int lo, int hi) {
    return min(max(v, lo), hi);
}

// ---------------------------------------------------------------------------
// k1: luma + downsample 1080x1920 -> 540x960, 2 outputs/thread (cols tx, tx+32)
// ---------------------------------------------------------------------------
__global__ void __launch_bounds__(256) k_luma_half(const float* __restrict__ img) {
    int jbase = blockIdx.x * 64 + threadIdx.x;
    int i = blockIdx.y * 8 + threadIdx.y;
    int b = blockIdx.z;
    if (i >= SH_) return;

    float ys = fminf((float)i * (1079.0f / 539.0f), 1079.0f);
    int y0 = (int)ys;
    int y1 = min(y0 + 1, H_ - 1);
    float wy = ys - (float)y0;

    const float* r0c = img + (size_t)b * 3 * HW_;
    const float* g0c = r0c + HW_;
    const float* b0c = r0c + 2 * HW_;

#pragma unroll
    for (int s = 0; s < 2; s++) {
        int j = jbase + s * 32;
        float xs = fminf((float)j * (1919.0f / 959.0f), 1919.0f);
        int x0 = (int)xs;
        int x1 = min(x0 + 1, W_ - 1);
        float wx = xs - (float)x0;

        int i00 = y0 * W_ + x0, i01 = y0 * W_ + x1;
        int i10 = y1 * W_ + x0, i11 = y1 * W_ + x1;
        float v00 = 0.299f*__ldg(r0c+i00) + 0.587f*__ldg(g0c+i00) + 0.114f*__ldg(b0c+i00);
        float v01 = 0.299f*__ldg(r0c+i01) + 0.587f*__ldg(g0c+i01) + 0.114f*__ldg(b0c+i01);
        float v10 = 0.299f*__ldg(r0c+i10) + 0.587f*__ldg(g0c+i10) + 0.114f*__ldg(b0c+i10);
        float v11 = 0.299f*__ldg(r0c+i11) + 0.587f*__ldg(g0c+i11) + 0.114f*__ldg(b0c+i11);

        float v = (v00 * (1.f - wx) + v01 * wx) * (1.f - wy)
                + (v10 * (1.f - wx) + v11 * wx) * wy;
        g_luma[(size_t)b * SHW_ + (size_t)i * SW_ + j] = v;
    }
}

// ---------------------------------------------------------------------------
// k2: fused field kernel on 32x32 tiles (unchanged from R5 best):
//     luma tile -> edge sobel -> gaussian H -> gaussian V -> grad sobel
// ---------------------------------------------------------------------------
__global__ void __launch_bounds__(256) k_field() {
    __shared__ float sL[40][41];
    __shared__ float sE[38][39];
    __shared__ float sH[38][35];
    __shared__ float sV[34][35];

    int j0 = blockIdx.x * 32;
    int i0 = blockIdx.y * 32;
    int b  = blockIdx.z;
    int tid = threadIdx.y * 32 + threadIdx.x;

    const float* lp = g_luma + (size_t)b * SHW_;

    for (int t = tid; t < 40 * 40; t += 256) {
        int r = t / 40, c = t % 40;
        int gi = iclamp(i0 - 4 + r, 0, SH_ - 1);
        int gj = iclamp(j0 - 4 + c, 0, SW_ - 1);
        sL[r][c] = __ldg(lp + (size_t)gi * SW_ + gj);
    }
    __syncthreads();

    for (int t = tid; t < 38 * 38; t += 256) {
        int er = t / 38, ec = t % 38;
        int ci = iclamp(i0 - 3 + er, 0, SH_ - 1);
        int cj = iclamp(j0 - 3 + ec, 0, SW_ - 1);
        int rm = max(ci - 1, 0)        - (i0 - 4);
        int rc = ci                    - (i0 - 4);
        int rp = min(ci + 1, SH_ - 1)  - (i0 - 4);
        int cm = max(cj - 1, 0)        - (j0 - 4);
        int cc = cj                    - (j0 - 4);
        int cp = min(cj + 1, SW_ - 1)  - (j0 - 4);

        float gxm = SXE * (sL[rm][cp] - sL[rm][cm]);
        float gxc = SXE * (sL[rc][cp] - sL[rc][cm]);
        float gxp = SXE * (sL[rp][cp] - sL[rp][cm]);
        float gsm = SXE * (sL[rm][cm] + sL[rm][cp]) + (4.f - 2.f * SXE) * sL[rm][cc];
        float gsp = SXE * (sL[rp][cm] + sL[rp][cp]) + (4.f - 2.f * SXE) * sL[rp][cc];

        float xg = 0.125f * (SYE * (gxm + gxp) + (4.f - 2.f * SYE) * gxc);
        float yg = 0.125f * SYE * (gsp - gsm);
        float m2 = xg * xg + yg * yg;
        sE[er][ec] = exp2f(0.35f * __log2f(m2));   // (m2)^0.35 == mag^0.7
    }
    __syncthreads();

    for (int t = tid; t < 38 * 34; t += 256) {
        int hr = t / 34, hc = t % 34;
        int cj = iclamp(j0 - 1 + hc, 0, SW_ - 1);
        int c0 = max(cj - 2, 0)       - (j0 - 3);
        int c1 = max(cj - 1, 0)       - (j0 - 3);
        int c2 = cj                   - (j0 - 3);
        int c3 = min(cj + 1, SW_ - 1) - (j0 - 3);
        int c4 = min(cj + 2, SW_ - 1) - (j0 - 3);
        sH[hr][hc] = GW2 * (sE[hr][c0] + sE[hr][c4])
                   + GW1 * (sE[hr][c1] + sE[hr][c3])
                   + GW0 * sE[hr][c2];
    }
    __syncthreads();

    for (int t = tid; t < 34 * 34; t += 256) {
        int vr = t / 34, hc = t % 34;
        int ci = iclamp(i0 - 1 + vr, 0, SH_ - 1);
        int r0 = max(ci - 2, 0)       - (i0 - 3);
        int r1 = max(ci - 1, 0)       - (i0 - 3);
        int r2 = ci                   - (i0 - 3);
        int r3 = min(ci + 1, SH_ - 1) - (i0 - 3);
        int r4 = min(ci + 2, SH_ - 1) - (i0 - 3);
        sV[vr][hc] = GW2 * (sH[r0][hc] + sH[r4][hc])
                   + GW1 * (sH[r1][hc] + sH[r3][hc])
                   + GW0 * sH[r2][hc];
    }
    __syncthreads();

    for (int t = tid; t < 32 * 32; t += 256) {
        int gr = t / 32, gc = t % 32;
        int i = i0 + gr, j = j0 + gc;
        if (i >= SH_ || j >= SW_) continue;
        int rm = max(i - 1, 0)        - (i0 - 1);
        int rc = i                    - (i0 - 1);
        int rp = min(i + 1, SH_ - 1)  - (i0 - 1);
        int cm = max(j - 1, 0)        - (j0 - 1);
        int cc = j                    - (j0 - 1);
        int cp = min(j + 1, SW_ - 1)  - (j0 - 1);

        float gxm = SXG * (sV[rm][cp] - sV[rm][cm]);
        float gxc = SXG * (sV[rc][cp] - sV[rc][cm]);
        float gxp = SXG * (sV[rp][cp] - sV[rp][cm]);
        float gsm = SXG * (sV[rm][cm] + sV[rm][cp]) + (4.f - 2.f * SXG) * sV[rm][cc];
        float gsp = SXG * (sV[rp][cm] + sV[rp][cp]) + (4.f - 2.f * SXG) * sV[rp][cc];

        float xg = 0.125f * (SYG * (gxm + gxp) + (4.f - 2.f * SYG) * gxc);
        float yg = 0.125f * SYG * (gsp - gsm);
        g_grad_half[(size_t)b * SHW_ + (size_t)i * SW_ + j] = make_float2(xg, yg);
    }
}

// ---------------------------------------------------------------------------
// k3: fused resize + warp + sample, 32x32 tile, 4 px/thread
//     (rows ty, ty+8, ty+16, ty+24). Loop body identical to R5 best
//     (smem bilinear loads); 4 independent chains for ILP.
// ---------------------------------------------------------------------------
#define SMW 34
#define SMH 34

__global__ void __launch_bounds__(256) k_warp_fused(const float* __restrict__ img,
                                                    float* __restrict__ out) {
    __shared__ float2 sg[SMH][SMW];

    int j0 = blockIdx.x * 32;
    int i0 = blockIdx.y * 32;
    int b  = blockIdx.z;
    int tx = threadIdx.x, ty = threadIdx.y;
    int tid = ty * 32 + tx;

    const float2* gh = g_grad_half + (size_t)b * SHW_;

    // fill full-res grad lattice patch [i0-1, i0+32] x [j0-1, j0+32]
    for (int t = tid; t < SMW * SMH; t += 256) {
        int sy = t / SMW, sx = t % SMW;
        int I = iclamp(i0 - 1 + sy, 0, H_ - 1);
        int J = iclamp(j0 - 1 + sx, 0, W_ - 1);

        float ys = fminf((float)I * (539.0f / 1079.0f), (float)(SH_ - 1));
        float xs = fminf((float)J * (959.0f / 1919.0f), (float)(SW_ - 1));
        int y0 = (int)ys, x0 = (int)xs;
        int y1 = min(y0 + 1, SH_ - 1), x1 = min(x0 + 1, SW_ - 1);
        float wy = ys - (float)y0, wx = xs - (float)x0;

        float2 v00 = __ldg(&gh[(size_t)y0 * SW_ + x0]);
        float2 v01 = __ldg(&gh[(size_t)y0 * SW_ + x1]);
        float2 v10 = __ldg(&gh[(size_t)y1 * SW_ + x0]);
        float2 v11 = __ldg(&gh[(size_t)y1 * SW_ + x1]);
        float2 r;
        r.x = (v00.x * (1.f - wx) + v01.x * wx) * (1.f - wy)
            + (v10.x * (1.f - wx) + v11.x * wx) * wy;
        r.y = (v00.y * (1.f - wx) + v01.y * wx) * (1.f - wy)
            + (v10.y * (1.f - wx) + v11.y * wx) * wy;
        sg[sy][sx] = r;
    }
    __syncthreads();

    int j = j0 + tx;

    const float stx = 0.1f * (float)(W_ - 1) / (float)W_;
    const float sty = 0.1f * (float)(H_ - 1) / (float)H_;

    float px[4], py[4];
#pragma unroll
    for (int s = 0; s < 4; s++) {
        px[s] = (float)j;
        py[s] = (float)(i0 + ty + s * 8);
    }

#pragma unroll
    for (int it = 0; it < 6; it++) {
#pragma unroll
        for (int s = 0; s < 4; s++) {
            float xc = fminf(fmaxf(px[s], 0.f), (float)(W_ - 1));
            float yc = fminf(fmaxf(py[s], 0.f), (float)(H_ - 1));
            int x0 = (int)xc, y0 = (int)yc;
            float wx = xc - (float)x0, wy = yc - (float)y0;
            int sx0 = x0 - (j0 - 1), sy0 = y0 - (i0 - 1);
            sy0 = min(sy0, SMH - 2);
            int sx1 = min(sx0 + 1, SMW - 1), sy1 = sy0 + 1;
            float2 v00 = sg[sy0][sx0], v01 = sg[sy0][sx1];
            float2 v10 = sg[sy1][sx0], v11 = sg[sy1][sx1];
            float dx = (v00.x * (1.f - wx) + v01.x * wx) * (1.f - wy)
                     + (v10.x * (1.f - wx) + v11.x * wx) * wy;
            float dy = (v00.y * (1.f - wx) + v01.y * wx) * (1.f - wy)
                     + (v10.y * (1.f - wx) + v11.y * wx) * wy;
            float inv = 1.f / (sqrtf(dx * dx + dy * dy) + 0.01f);
            px[s] -= dx * inv * stx;
            py[s] -= dy * inv * sty;
        }
    }

    // final image sample (3 channels, global/L1) + clip, all 4 rows
#pragma unroll
    for (int s = 0; s < 4; s++) {
        int i = i0 + ty + s * 8;
        if (i >= H_) break;

        float xc = fminf(fmaxf(px[s], 0.f), (float)(W_ - 1));
        float yc = fminf(fmaxf(py[s], 0.f), (float)(H_ - 1));
        int x0 = (int)xc, y0 = (int)yc;
        int x1 = min(x0 + 1, W_ - 1), y1 = min(y0 + 1, H_ - 1);
        float wx = xc - (float)x0, wy = yc - (float)y0;
        float w00 = (1.f - wx) * (1.f - wy), w01 = wx * (1.f - wy);
        float w10 = (1.f - wx) * wy,         w11 = wx * wy;
        size_t i00 = (size_t)y0 * W_ + x0, i01 = (size_t)y0 * W_ + x1;
        size_t i10 = (size_t)y1 * W_ + x0, i11 = (size_t)y1 * W_ + x1;

#pragma unroll
        for (int c = 0; c < 3; c++) {
            const float* plane = img + ((size_t)b * 3 + c) * HW_;
            float v = __ldg(plane + i00) * w00 + __ldg(plane + i01) * w01
                    + __ldg(plane + i10) * w10 + __ldg(plane + i11) * w11;
            v = fminf(fmaxf(v, 0.f), 1.f);
            out[((size_t)b * 3 + c) * HW_ + (size_t)i * W_ + j] = v;
        }
    }
}

// ---------------------------------------------------------------------------
extern "C" void kernel_launch(void* const* d_in, const int* in_sizes, int n_in,
                              void* d_out, int out_size) {
    const float* img = (const float*)d_in[0];
    float* out = (float*)d_out;

    dim3 blk(32, 8, 1);
    dim3 gridL(SW_ / 64, (SH_ + 7) / 8, B_);
    dim3 gridS((SW_ + 31) / 32, (SH_ + 31) / 32, B_);
    dim3 gridF(W_ / 32, (H_ + 31) / 32, B_);

    k_luma_half <<<gridL, blk>>>(img);
    k_field     <<<gridS, blk>>>();
    k_warp_fused<<<gridF, blk>>>(img, out);
}